// round 14
// baseline (speedup 1.0000x reference)
#include <cuda_runtime.h>
#include <cuda_fp16.h>
#include <cstdint>

#define BATCH   16384
#define NF      768
#define FT      1024
#define NROWS   (2*BATCH)      // virtual rows: [0,16384)=stm, [16384,32768)=nstm
#define MAXI    128            // max stored nonzeros per row (mean 32)
#define NSL     8              // output slices
#define OSL     128            // outputs per slice
#define RB      18             // blocks per slice: 8*18 = 144 blocks = 1 wave
#define THREADS 1024           // 32 warps: 1 warp per row
#define WARPS   32
#define STRIDE  (RB * WARPS)   // 576
#define NSLOT   16             // 8 slices x 2 perspectives
#define SMEM_W  ((NF + 1) * OSL * 2)       // 196,864 B fp16 W slice (+ zero dummy row)
#define SMEM_BYTES (SMEM_W + 256 * 4)      // + W_out table (2 persp x 128 outs)

// ---- scratch (device globals; no allocation) ----
__device__ uint16_t g_idx[(size_t)NROWS * MAXI];   // 8 MB compacted indices (padded to x4)
__device__ int      g_cnt[NROWS];                  // PADDED counts (multiple of 4)
__device__ float    g_acc[(size_t)BATCH * NSLOT];  // [batch][slot], contiguous per board
__device__ unsigned g_done[BATCH];                 // completion counters (monotonic;
                                                   // +16 per board per launch -> no reset)

// ============================================================================
// Kernel 1 (champion): warp-per-row scan with smem-staged coalesced output.
// Mask/prefix-scan; emit into per-warp smem buffer pre-filled with 48 dummies;
// flush as 6x STG.128 (3 full sectors). Rare cnt>48 tail: guarded scalars.
// ============================================================================
__global__ __launch_bounds__(256) void scan_kernel(const float* __restrict__ stm,
                                                   const float* __restrict__ nstm) {
    __shared__ uint16_t stage[8][128];               // 2 KB: per-warp staging
    int gtid = blockIdx.x * 256 + threadIdx.x;
    int warp = gtid >> 5;
    int lane = gtid & 31;
    if (warp >= NROWS) return;
    uint16_t* st = stage[threadIdx.x >> 5];

    const float* row = (warp < BATCH) ? (stm + (size_t)warp * NF)
                                      : (nstm + (size_t)(warp - BATCH) * NF);
    const float4* row4 = (const float4*)row;

    // pre-fill first 48 staging slots with dummy NF (lanes 0..23, 2 each)
    if (lane < 24) ((uint32_t*)st)[lane] = (uint32_t)NF | ((uint32_t)NF << 16);

    unsigned mask = 0;
    #pragma unroll
    for (int j = 0; j < 6; j++) {                    // coalesced: 32 lanes x 16B
        float4 v = row4[lane + 32 * j];
        if (v.x != 0.0f) mask |= 1u << (4 * j + 0);
        if (v.y != 0.0f) mask |= 1u << (4 * j + 1);
        if (v.z != 0.0f) mask |= 1u << (4 * j + 2);
        if (v.w != 0.0f) mask |= 1u << (4 * j + 3);
    }
    int cl = __popc(mask);

    int pre = cl;                                    // warp inclusive scan
    #pragma unroll
    for (int off = 1; off < 32; off <<= 1) {
        int n = __shfl_up_sync(0xffffffffu, pre, off);
        if (lane >= off) pre += n;
    }
    int excl  = pre - cl;
    int total = __shfl_sync(0xffffffffu, pre, 31);
    __syncwarp();                                    // dummy pre-fill done

    int basep = excl;                                // avg ~1 bit/lane -> short loop
    while (mask) {
        int b = __ffs(mask) - 1;
        mask &= mask - 1;
        if (basep < MAXI)
            st[basep] = (uint16_t)((lane << 2) + ((b >> 2) << 7) + (b & 3));
        basep++;
    }
    __syncwarp();                                    // staging complete

    int cnt = (total < MAXI) ? total : MAXI;
    int pc = (cnt + 3) & ~3;
    if (pc > MAXI) pc = MAXI;

    // coalesced flush: 6 x STG.128 = indices [0,48) incl. dummy padding
    uint16_t* out = g_idx + (size_t)warp * MAXI;
    if (lane < 6) ((uint4*)out)[lane] = ((const uint4*)st)[lane];
    if (pc > 48) {                                   // rare tail (~0.2% of rows)
        for (int k = 48 + lane; k < pc; k += 32)
            out[k] = (k < cnt) ? st[k] : (uint16_t)NF;
    }
    if (lane == 0) g_cnt[warp] = pc;
}

// ============================================================================
// Kernel 2: champion accumulate + FUSED FINALIZE.
// Gather core unchanged (32 warps, 1 warp/row, LDS.64, 4 HADD2 chains).
// After the deterministic slot write, lane 0 does a release atomicAdd on the
// board's completion counter; the 16th completer (acquire) re-reads all 16
// slots in fixed order (__ldcg), adds b_out, applies sigmoid, stores out[b].
// Counter is monotonic (+16/board/launch) -> graph-replay safe, no reset.
// ============================================================================
__global__ __launch_bounds__(THREADS, 1) void accum_kernel(const float* __restrict__ W_ft,
                                                           const float* __restrict__ b_ft,
                                                           const float* __restrict__ W_out,
                                                           const float* __restrict__ b_out,
                                                           float* __restrict__ out) {
    extern __shared__ __half W_sm[];   // [(NF+1)][OSL] then float wc[2][128]

    const int s  = blockIdx.x / RB;
    const int rg = blockIdx.x % RB;
    const int obase = s * OSL;
    float* wc = (float*)((char*)W_sm + SMEM_W);

    for (int p = threadIdx.x; p < 64 * (NF / 4); p += THREADS) {
        int fq = p >> 6;                 // 0..191
        int op = (p & 63) << 1;          // even output 0..126
        float4 a = *(const float4*)(W_ft + (size_t)(obase + op)     * NF + 4 * fq);
        float4 b = *(const float4*)(W_ft + (size_t)(obase + op + 1) * NF + 4 * fq);
        __half2* dst = (__half2*)W_sm;
        int w0 = (4 * fq) * (OSL / 2) + (op >> 1);
        dst[w0            ] = __floats2half2_rn(a.x, b.x);
        dst[w0 + OSL / 2  ] = __floats2half2_rn(a.y, b.y);
        dst[w0 + OSL      ] = __floats2half2_rn(a.z, b.z);
        dst[w0 + 3*OSL / 2] = __floats2half2_rn(a.w, b.w);
    }
    if (threadIdx.x < OSL / 2)           // zero dummy row NF
        ((__half2*)W_sm)[NF * (OSL / 2) + threadIdx.x] = __floats2half2_rn(0.f, 0.f);
    if (threadIdx.x < 256)               // W_out table: [persp][out in slice]
        wc[threadIdx.x] = W_out[(threadIdx.x >> 7) * FT + obase + (threadIdx.x & 127)];
    __syncthreads();

    const int w    = threadIdx.x >> 5;
    const int lane = threadIdx.x & 31;
    const float4 bf = *(const float4*)(b_ft + obase + lane * 4);
    const float bo  = b_out[0];
    const char* Wl = (const char*)W_sm + lane * 8;
    const float* wcl = wc + lane * 4;

    for (int R = rg * WARPS + w; R < NROWS; R += STRIDE) {
        const int cnt = g_cnt[R];                    // padded (multiple of 4)
        const uint4* ip4 = (const uint4*)(g_idx + (size_t)R * MAXI);

        uint4 u0 = ip4[0], u1 = ip4[1], u2 = ip4[2],
              u3 = ip4[3], u4 = ip4[4], u5 = ip4[5];

        __half2 z = __floats2half2_rn(0.f, 0.f);
        __half2 aa0 = z, aa1 = z, ba0 = z, ba1 = z;
        __half2 ca0 = z, ca1 = z, da0 = z, da1 = z;
        const int ng = cnt >> 2;

        #define G1(IDX, A0, A1) { \
            uint2 v = *(const uint2*)(Wl + (int)(IDX) * (OSL * 2)); \
            A0 = __hadd2(A0, *(__half2*)&v.x); A1 = __hadd2(A1, *(__half2*)&v.y); }
        #define GRP4(LO, HI) { \
            G1(LO & 0xffffu, aa0, aa1)  G1(LO >> 16, ba0, ba1) \
            G1(HI & 0xffffu, ca0, ca1)  G1(HI >> 16, da0, da1) }

        if (ng >  0) GRP4(u0.x, u0.y)
        if (ng >  1) GRP4(u0.z, u0.w)
        if (ng >  2) GRP4(u1.x, u1.y)
        if (ng >  3) GRP4(u1.z, u1.w)
        if (ng >  4) GRP4(u2.x, u2.y)
        if (ng >  5) GRP4(u2.z, u2.w)
        if (ng >  6) GRP4(u3.x, u3.y)
        if (ng >  7) GRP4(u3.z, u3.w)
        if (ng >  8) GRP4(u4.x, u4.y)
        if (ng >  9) GRP4(u4.z, u4.w)
        if (ng > 10) GRP4(u5.x, u5.y)
        if (ng > 11) GRP4(u5.z, u5.w)
        if (cnt > 48) {
            const uint16_t* ip = (const uint16_t*)ip4;
            for (int k = 48; k < cnt; k++)
                G1(ip[k], aa0, aa1)
        }
        #undef GRP4
        #undef G1

        float2 f0 = __half22float2(aa0), f1 = __half22float2(ba0);
        float2 f2 = __half22float2(ca0), f3 = __half22float2(da0);
        float2 g0 = __half22float2(aa1), g1 = __half22float2(ba1);
        float2 g2 = __half22float2(ca1), g3 = __half22float2(da1);
        float p0 = fminf(fmaxf(bf.x + (f0.x + f1.x) + (f2.x + f3.x), 0.f), 1.f);
        float p1 = fminf(fmaxf(bf.y + (f0.y + f1.y) + (f2.y + f3.y), 0.f), 1.f);
        float p2 = fminf(fmaxf(bf.z + (g0.x + g1.x) + (g2.x + g3.x), 0.f), 1.f);
        float p3 = fminf(fmaxf(bf.w + (g0.y + g1.y) + (g2.y + g3.y), 0.f), 1.f);
        const int pr = (R >= BATCH);
        const float4 wo = *(const float4*)(wcl + pr * 128);
        float contrib = p0*p0*wo.x + p1*p1*wo.y + p2*p2*wo.z + p3*p3*wo.w;

        #pragma unroll
        for (int off = 16; off; off >>= 1)
            contrib += __shfl_xor_sync(0xffffffffu, contrib, off);

        if (lane == 0) {
            const int b = R & (BATCH - 1);
            g_acc[(size_t)b * NSLOT + (s * 2 + pr)] = contrib;

            // release: order the slot store before the counter bump
            unsigned old;
            asm volatile("atom.acq_rel.gpu.global.add.u32 %0, [%1], 1;"
                         : "=r"(old) : "l"(&g_done[b]) : "memory");
            if ((old & 15u) == 15u) {
                // 16th completer: all slot writes visible (acq_rel chain).
                const float4* a4 = (const float4*)(g_acc + (size_t)b * NSLOT);
                float4 v0 = __ldcg(a4 + 0), v1 = __ldcg(a4 + 1);
                float4 v2 = __ldcg(a4 + 2), v3 = __ldcg(a4 + 3);
                float x = bo
                        + ((v0.x + v0.y) + (v0.z + v0.w))
                        + ((v1.x + v1.y) + (v1.z + v1.w))
                        + ((v2.x + v2.y) + (v2.z + v2.w))
                        + ((v3.x + v3.y) + (v3.z + v3.w));
                out[b] = 1.0f / (1.0f + expf(-x));
            }
        }
    }
}

extern "C" void kernel_launch(void* const* d_in, const int* in_sizes, int n_in,
                              void* d_out, int out_size) {
    const float* stm   = (const float*)d_in[0];
    const float* nstm  = (const float*)d_in[1];
    const float* W_ft  = (const float*)d_in[2];
    const float* b_ft  = (const float*)d_in[3];
    const float* W_out = (const float*)d_in[4];
    const float* b_out = (const float*)d_in[5];
    float* out = (float*)d_out;

    cudaFuncSetAttribute(accum_kernel,
                         cudaFuncAttributeMaxDynamicSharedMemorySize, SMEM_BYTES);

    scan_kernel<<<NROWS / 8, 256>>>(stm, nstm);                                // 4096 blocks
    accum_kernel<<<NSL * RB, THREADS, SMEM_BYTES>>>(W_ft, b_ft, W_out, b_out, out);
}

// round 16
// speedup vs baseline: 1.4198x; 1.4198x over previous
#include <cuda_runtime.h>
#include <cuda_fp16.h>
#include <cstdint>

#define BATCH   16384
#define NF      768
#define FT      1024
#define NROWS   (2*BATCH)      // virtual rows: [0,16384)=stm, [16384,32768)=nstm
#define MAXI    128            // max stored nonzeros per row (mean 32)
#define NSL     8              // output slices
#define OSL     128            // outputs per slice
#define RB      18             // blocks per slice: 8*18 = 144 blocks = 1 wave
#define THREADS 1024           // 32 warps: 1 warp per row
#define WARPS   32
#define STRIDE  (RB * WARPS)   // 576
#define NSLOT   16             // 8 slices x 2 perspectives
#define SMEM_W  ((NF + 1) * OSL * 2)       // 196,864 B fp16 W slice (+ zero dummy row)
#define SMEM_BYTES (SMEM_W + 256 * 4)      // + W_out table (2 persp x 128 outs)

// ---- scratch (device globals; no allocation) ----
__device__ uint16_t g_idx[(size_t)NROWS * MAXI];   // 8 MB compacted indices (padded to x4)
__device__ int      g_cnt[NROWS];                  // PADDED counts (multiple of 4)
__device__ float    g_acc[(size_t)BATCH * NSLOT];  // [batch][slot] -> finalize reads 4x float4

// ============================================================================
// Kernel 1 (champion): warp-per-row scan with smem-staged coalesced output.
// Mask/prefix-scan; emit into per-warp smem buffer pre-filled with 48 dummies;
// flush as 6x STG.128 (3 full sectors). Rare cnt>48 tail: guarded scalars.
// ============================================================================
__global__ __launch_bounds__(256) void scan_kernel(const float* __restrict__ stm,
                                                   const float* __restrict__ nstm) {
    __shared__ uint16_t stage[8][128];               // 2 KB: per-warp staging
    int gtid = blockIdx.x * 256 + threadIdx.x;
    int warp = gtid >> 5;
    int lane = gtid & 31;
    if (warp >= NROWS) return;
    uint16_t* st = stage[threadIdx.x >> 5];

    const float* row = (warp < BATCH) ? (stm + (size_t)warp * NF)
                                      : (nstm + (size_t)(warp - BATCH) * NF);
    const float4* row4 = (const float4*)row;

    // pre-fill first 48 staging slots with dummy NF (lanes 0..23, 2 each)
    if (lane < 24) ((uint32_t*)st)[lane] = (uint32_t)NF | ((uint32_t)NF << 16);

    unsigned mask = 0;
    #pragma unroll
    for (int j = 0; j < 6; j++) {                    // coalesced: 32 lanes x 16B
        float4 v = row4[lane + 32 * j];
        if (v.x != 0.0f) mask |= 1u << (4 * j + 0);
        if (v.y != 0.0f) mask |= 1u << (4 * j + 1);
        if (v.z != 0.0f) mask |= 1u << (4 * j + 2);
        if (v.w != 0.0f) mask |= 1u << (4 * j + 3);
    }
    int cl = __popc(mask);

    int pre = cl;                                    // warp inclusive scan
    #pragma unroll
    for (int off = 1; off < 32; off <<= 1) {
        int n = __shfl_up_sync(0xffffffffu, pre, off);
        if (lane >= off) pre += n;
    }
    int excl  = pre - cl;
    int total = __shfl_sync(0xffffffffu, pre, 31);
    __syncwarp();                                    // dummy pre-fill done

    int basep = excl;                                // avg ~1 bit/lane -> short loop
    while (mask) {
        int b = __ffs(mask) - 1;
        mask &= mask - 1;
        if (basep < MAXI)
            st[basep] = (uint16_t)((lane << 2) + ((b >> 2) << 7) + (b & 3));
        basep++;
    }
    __syncwarp();                                    // staging complete

    int cnt = (total < MAXI) ? total : MAXI;
    int pc = (cnt + 3) & ~3;
    if (pc > MAXI) pc = MAXI;

    // coalesced flush: 6 x STG.128 = indices [0,48) incl. dummy padding
    uint16_t* out = g_idx + (size_t)warp * MAXI;
    if (lane < 6) ((uint4*)out)[lane] = ((const uint4*)st)[lane];
    if (pc > 48) {                                   // rare tail (~0.2% of rows)
        for (int k = 48 + lane; k < pc; k += 32)
            out[k] = (k < cnt) ? st[k] : (uint16_t)NF;
    }
    if (lane == 0) g_cnt[warp] = pc;
}

// ============================================================================
// Kernel 2 (UNCHANGED champion): sparse accumulate from fp16 smem W slice.
// 32 warps, 1 warp/row, lane l serves outputs {4l..4l+3} via LDS.64; 6x uint4
// unconditional index prefetch; x4 groups; 4 independent HADD2 chains; fused
// SCReLU/W_out epilogue; deterministic slot writes (g_acc [batch][slot]).
// Confirmed ~95% of L1/crossbar throughput peak (R14 profile scaling).
// ============================================================================
__global__ __launch_bounds__(THREADS, 1) void accum_kernel(const float* __restrict__ W_ft,
                                                           const float* __restrict__ b_ft,
                                                           const float* __restrict__ W_out) {
    extern __shared__ __half W_sm[];   // [(NF+1)][OSL] then float wc[2][128]

    const int s  = blockIdx.x / RB;
    const int rg = blockIdx.x % RB;
    const int obase = s * OSL;
    float* wc = (float*)((char*)W_sm + SMEM_W);

    for (int p = threadIdx.x; p < 64 * (NF / 4); p += THREADS) {
        int fq = p >> 6;                 // 0..191
        int op = (p & 63) << 1;          // even output 0..126
        float4 a = *(const float4*)(W_ft + (size_t)(obase + op)     * NF + 4 * fq);
        float4 b = *(const float4*)(W_ft + (size_t)(obase + op + 1) * NF + 4 * fq);
        __half2* dst = (__half2*)W_sm;
        int w0 = (4 * fq) * (OSL / 2) + (op >> 1);
        dst[w0            ] = __floats2half2_rn(a.x, b.x);
        dst[w0 + OSL / 2  ] = __floats2half2_rn(a.y, b.y);
        dst[w0 + OSL      ] = __floats2half2_rn(a.z, b.z);
        dst[w0 + 3*OSL / 2] = __floats2half2_rn(a.w, b.w);
    }
    if (threadIdx.x < OSL / 2)           // zero dummy row NF
        ((__half2*)W_sm)[NF * (OSL / 2) + threadIdx.x] = __floats2half2_rn(0.f, 0.f);
    if (threadIdx.x < 256)               // W_out table: [persp][out in slice]
        wc[threadIdx.x] = W_out[(threadIdx.x >> 7) * FT + obase + (threadIdx.x & 127)];
    __syncthreads();

    const int w    = threadIdx.x >> 5;
    const int lane = threadIdx.x & 31;
    const float4 bf = *(const float4*)(b_ft + obase + lane * 4);
    const char* Wl = (const char*)W_sm + lane * 8;
    const float* wcl = wc + lane * 4;

    for (int R = rg * WARPS + w; R < NROWS; R += STRIDE) {
        const int cnt = g_cnt[R];                    // padded (multiple of 4)
        const uint4* ip4 = (const uint4*)(g_idx + (size_t)R * MAXI);

        uint4 u0 = ip4[0], u1 = ip4[1], u2 = ip4[2],
              u3 = ip4[3], u4 = ip4[4], u5 = ip4[5];

        __half2 z = __floats2half2_rn(0.f, 0.f);
        __half2 aa0 = z, aa1 = z, ba0 = z, ba1 = z;
        __half2 ca0 = z, ca1 = z, da0 = z, da1 = z;
        const int ng = cnt >> 2;

        #define G1(IDX, A0, A1) { \
            uint2 v = *(const uint2*)(Wl + (int)(IDX) * (OSL * 2)); \
            A0 = __hadd2(A0, *(__half2*)&v.x); A1 = __hadd2(A1, *(__half2*)&v.y); }
        #define GRP4(LO, HI) { \
            G1(LO & 0xffffu, aa0, aa1)  G1(LO >> 16, ba0, ba1) \
            G1(HI & 0xffffu, ca0, ca1)  G1(HI >> 16, da0, da1) }

        if (ng >  0) GRP4(u0.x, u0.y)
        if (ng >  1) GRP4(u0.z, u0.w)
        if (ng >  2) GRP4(u1.x, u1.y)
        if (ng >  3) GRP4(u1.z, u1.w)
        if (ng >  4) GRP4(u2.x, u2.y)
        if (ng >  5) GRP4(u2.z, u2.w)
        if (ng >  6) GRP4(u3.x, u3.y)
        if (ng >  7) GRP4(u3.z, u3.w)
        if (ng >  8) GRP4(u4.x, u4.y)
        if (ng >  9) GRP4(u4.z, u4.w)
        if (ng > 10) GRP4(u5.x, u5.y)
        if (ng > 11) GRP4(u5.z, u5.w)
        if (cnt > 48) {
            const uint16_t* ip = (const uint16_t*)ip4;
            for (int k = 48; k < cnt; k++)
                G1(ip[k], aa0, aa1)
        }
        #undef GRP4
        #undef G1

        float2 f0 = __half22float2(aa0), f1 = __half22float2(ba0);
        float2 f2 = __half22float2(ca0), f3 = __half22float2(da0);
        float2 g0 = __half22float2(aa1), g1 = __half22float2(ba1);
        float2 g2 = __half22float2(ca1), g3 = __half22float2(da1);
        float p0 = fminf(fmaxf(bf.x + (f0.x + f1.x) + (f2.x + f3.x), 0.f), 1.f);
        float p1 = fminf(fmaxf(bf.y + (f0.y + f1.y) + (f2.y + f3.y), 0.f), 1.f);
        float p2 = fminf(fmaxf(bf.z + (g0.x + g1.x) + (g2.x + g3.x), 0.f), 1.f);
        float p3 = fminf(fmaxf(bf.w + (g0.y + g1.y) + (g2.y + g3.y), 0.f), 1.f);
        const int pr = (R >= BATCH);
        const float4 wo = *(const float4*)(wcl + pr * 128);
        float contrib = p0*p0*wo.x + p1*p1*wo.y + p2*p2*wo.z + p3*p3*wo.w;

        #pragma unroll
        for (int off = 16; off; off >>= 1)
            contrib += __shfl_xor_sync(0xffffffffu, contrib, off);

        if (lane == 0)
            g_acc[(size_t)(R & (BATCH - 1)) * NSLOT + (s * 2 + pr)] = contrib;
    }
}

// ============================================================================
// Kernel 3: sum 16 contiguous partials (4x float4), add b_out, sigmoid.
// ============================================================================
__global__ __launch_bounds__(256) void finalize_kernel(const float* __restrict__ b_out,
                                                       float* __restrict__ out) {
    int b = blockIdx.x * 256 + threadIdx.x;
    if (b >= BATCH) return;
    const float4* a = (const float4*)(g_acc + (size_t)b * NSLOT);
    float4 v0 = a[0], v1 = a[1], v2 = a[2], v3 = a[3];
    float x = b_out[0]
            + ((v0.x + v0.y) + (v0.z + v0.w))
            + ((v1.x + v1.y) + (v1.z + v1.w))
            + ((v2.x + v2.y) + (v2.z + v2.w))
            + ((v3.x + v3.y) + (v3.z + v3.w));
    out[b] = 1.0f / (1.0f + __expf(-x));
}

extern "C" void kernel_launch(void* const* d_in, const int* in_sizes, int n_in,
                              void* d_out, int out_size) {
    const float* stm   = (const float*)d_in[0];
    const float* nstm  = (const float*)d_in[1];
    const float* W_ft  = (const float*)d_in[2];
    const float* b_ft  = (const float*)d_in[3];
    const float* W_out = (const float*)d_in[4];
    const float* b_out = (const float*)d_in[5];
    float* out = (float*)d_out;

    cudaFuncSetAttribute(accum_kernel,
                         cudaFuncAttributeMaxDynamicSharedMemorySize, SMEM_BYTES);

    scan_kernel<<<NROWS / 8, 256>>>(stm, nstm);                            // 4096 blocks
    accum_kernel<<<NSL * RB, THREADS, SMEM_BYTES>>>(W_ft, b_ft, W_out);    // 144 blocks
    finalize_kernel<<<(BATCH + 255) / 256, 256>>>(b_out, out);
}

// round 17
// speedup vs baseline: 1.4252x; 1.0038x over previous
#include <cuda_runtime.h>
#include <cuda_fp16.h>
#include <cstdint>

#define BATCH   16384
#define NF      768
#define FT      1024
#define NROWS   (2*BATCH)      // virtual rows: [0,16384)=stm, [16384,32768)=nstm
#define MAXI    128            // max stored nonzeros per row (mean 32)
#define NSL     8              // output slices
#define OSL     128            // outputs per slice
#define RB      18             // blocks per slice: 8*18 = 144 blocks = 1 wave
#define THREADS 1024           // 32 warps: 1 warp per row
#define WARPS   32
#define STRIDE  (RB * WARPS)   // 576
#define NSLOT   16             // 8 slices x 2 perspectives
#define SMEM_W  ((NF + 1) * OSL * 2)       // 196,864 B fp16 W slice (+ zero dummy row)
#define SMEM_BYTES (SMEM_W + 256 * 4)      // + W_out table (2 persp x 128 outs)

// ---- scratch (device globals; no allocation) ----
__device__ uint16_t g_idx[(size_t)NROWS * MAXI];   // 8 MB compacted indices (padded to x2)
__device__ int      g_cnt[NROWS];                  // PADDED counts (multiple of 2)
__device__ float    g_acc[(size_t)BATCH * NSLOT];  // [batch][slot] -> finalize reads 4x float4

// ============================================================================
// Kernel 1: warp-per-row scan with smem-staged coalesced output.
// Mask/prefix-scan; emit into per-warp smem buffer pre-filled with 48 dummies;
// flush as 6x STG.128 (3 full sectors). Counts padded to x2 (was x4): mean
// dummy gathers per row drop 1.5 -> 0.5, cutting ~3% of accum crossbar bytes.
// ============================================================================
__global__ __launch_bounds__(256) void scan_kernel(const float* __restrict__ stm,
                                                   const float* __restrict__ nstm) {
    __shared__ uint16_t stage[8][128];               // 2 KB: per-warp staging
    int gtid = blockIdx.x * 256 + threadIdx.x;
    int warp = gtid >> 5;
    int lane = gtid & 31;
    if (warp >= NROWS) return;
    uint16_t* st = stage[threadIdx.x >> 5];

    const float* row = (warp < BATCH) ? (stm + (size_t)warp * NF)
                                      : (nstm + (size_t)(warp - BATCH) * NF);
    const float4* row4 = (const float4*)row;

    // pre-fill first 48 staging slots with dummy NF (lanes 0..23, 2 each)
    if (lane < 24) ((uint32_t*)st)[lane] = (uint32_t)NF | ((uint32_t)NF << 16);

    unsigned mask = 0;
    #pragma unroll
    for (int j = 0; j < 6; j++) {                    // coalesced: 32 lanes x 16B
        float4 v = row4[lane + 32 * j];
        if (v.x != 0.0f) mask |= 1u << (4 * j + 0);
        if (v.y != 0.0f) mask |= 1u << (4 * j + 1);
        if (v.z != 0.0f) mask |= 1u << (4 * j + 2);
        if (v.w != 0.0f) mask |= 1u << (4 * j + 3);
    }
    int cl = __popc(mask);

    int pre = cl;                                    // warp inclusive scan
    #pragma unroll
    for (int off = 1; off < 32; off <<= 1) {
        int n = __shfl_up_sync(0xffffffffu, pre, off);
        if (lane >= off) pre += n;
    }
    int excl  = pre - cl;
    int total = __shfl_sync(0xffffffffu, pre, 31);
    __syncwarp();                                    // dummy pre-fill done

    int basep = excl;                                // avg ~1 bit/lane -> short loop
    while (mask) {
        int b = __ffs(mask) - 1;
        mask &= mask - 1;
        if (basep < MAXI)
            st[basep] = (uint16_t)((lane << 2) + ((b >> 2) << 7) + (b & 3));
        basep++;
    }
    __syncwarp();                                    // staging complete

    int cnt = (total < MAXI) ? total : MAXI;
    int pc = (cnt + 1) & ~1;                         // pad to x2 (was x4)
    if (pc > MAXI) pc = MAXI;

    // coalesced flush: 6 x STG.128 = indices [0,48) incl. dummy padding
    uint16_t* out = g_idx + (size_t)warp * MAXI;
    if (lane < 6) ((uint4*)out)[lane] = ((const uint4*)st)[lane];
    if (pc > 48) {                                   // rare tail (~0.2% of rows)
        for (int k = 48 + lane; k < pc; k += 32)
            out[k] = (k < cnt) ? st[k] : (uint16_t)NF;
    }
    if (lane == 0) g_cnt[warp] = pc;
}

// ============================================================================
// Kernel 2: champion gather core with x2-GRANULARITY groups (24 predicated
// 2-gather groups instead of 12 4-gather groups). Crossbar bytes -3%, issue
// +~6% -- favorable: R14 profile proved crossbar binds at ~95% while issue
// idles at 42%. Chains alternate (a,b)/(c,d) across words: ILP unchanged.
// ============================================================================
__global__ __launch_bounds__(THREADS, 1) void accum_kernel(const float* __restrict__ W_ft,
                                                           const float* __restrict__ b_ft,
                                                           const float* __restrict__ W_out) {
    extern __shared__ __half W_sm[];   // [(NF+1)][OSL] then float wc[2][128]

    const int s  = blockIdx.x / RB;
    const int rg = blockIdx.x % RB;
    const int obase = s * OSL;
    float* wc = (float*)((char*)W_sm + SMEM_W);

    for (int p = threadIdx.x; p < 64 * (NF / 4); p += THREADS) {
        int fq = p >> 6;                 // 0..191
        int op = (p & 63) << 1;          // even output 0..126
        float4 a = *(const float4*)(W_ft + (size_t)(obase + op)     * NF + 4 * fq);
        float4 b = *(const float4*)(W_ft + (size_t)(obase + op + 1) * NF + 4 * fq);
        __half2* dst = (__half2*)W_sm;
        int w0 = (4 * fq) * (OSL / 2) + (op >> 1);
        dst[w0            ] = __floats2half2_rn(a.x, b.x);
        dst[w0 + OSL / 2  ] = __floats2half2_rn(a.y, b.y);
        dst[w0 + OSL      ] = __floats2half2_rn(a.z, b.z);
        dst[w0 + 3*OSL / 2] = __floats2half2_rn(a.w, b.w);
    }
    if (threadIdx.x < OSL / 2)           // zero dummy row NF
        ((__half2*)W_sm)[NF * (OSL / 2) + threadIdx.x] = __floats2half2_rn(0.f, 0.f);
    if (threadIdx.x < 256)               // W_out table: [persp][out in slice]
        wc[threadIdx.x] = W_out[(threadIdx.x >> 7) * FT + obase + (threadIdx.x & 127)];
    __syncthreads();

    const int w    = threadIdx.x >> 5;
    const int lane = threadIdx.x & 31;
    const float4 bf = *(const float4*)(b_ft + obase + lane * 4);
    const char* Wl = (const char*)W_sm + lane * 8;
    const float* wcl = wc + lane * 4;

    for (int R = rg * WARPS + w; R < NROWS; R += STRIDE) {
        const int cnt = g_cnt[R];                    // padded (multiple of 2)
        const uint4* ip4 = (const uint4*)(g_idx + (size_t)R * MAXI);

        uint4 u0 = ip4[0], u1 = ip4[1], u2 = ip4[2],
              u3 = ip4[3], u4 = ip4[4], u5 = ip4[5];

        __half2 z = __floats2half2_rn(0.f, 0.f);
        __half2 aa0 = z, aa1 = z, ba0 = z, ba1 = z;
        __half2 ca0 = z, ca1 = z, da0 = z, da1 = z;
        const int nw = cnt >> 1;                     // index words (2 idx each)

        #define G1(IDX, A0, A1) { \
            uint2 v = *(const uint2*)(Wl + (int)(IDX) * (OSL * 2)); \
            A0 = __hadd2(A0, *(__half2*)&v.x); A1 = __hadd2(A1, *(__half2*)&v.y); }
        #define G2AB(W) { G1(W & 0xffffu, aa0, aa1)  G1(W >> 16, ba0, ba1) }
        #define G2CD(W) { G1(W & 0xffffu, ca0, ca1)  G1(W >> 16, da0, da1) }

        if (nw >  0) G2AB(u0.x)
        if (nw >  1) G2CD(u0.y)
        if (nw >  2) G2AB(u0.z)
        if (nw >  3) G2CD(u0.w)
        if (nw >  4) G2AB(u1.x)
        if (nw >  5) G2CD(u1.y)
        if (nw >  6) G2AB(u1.z)
        if (nw >  7) G2CD(u1.w)
        if (nw >  8) G2AB(u2.x)
        if (nw >  9) G2CD(u2.y)
        if (nw > 10) G2AB(u2.z)
        if (nw > 11) G2CD(u2.w)
        if (nw > 12) G2AB(u3.x)
        if (nw > 13) G2CD(u3.y)
        if (nw > 14) G2AB(u3.z)
        if (nw > 15) G2CD(u3.w)
        if (nw > 16) G2AB(u4.x)
        if (nw > 17) G2CD(u4.y)
        if (nw > 18) G2AB(u4.z)
        if (nw > 19) G2CD(u4.w)
        if (nw > 20) G2AB(u5.x)
        if (nw > 21) G2CD(u5.y)
        if (nw > 22) G2AB(u5.z)
        if (nw > 23) G2CD(u5.w)
        if (cnt > 48) {                              // rare tail (~0.2% of rows)
            const uint16_t* ip = (const uint16_t*)ip4;
            for (int k = 48; k < cnt; k++)
                G1(ip[k], aa0, aa1)
        }
        #undef G2CD
        #undef G2AB
        #undef G1

        float2 f0 = __half22float2(aa0), f1 = __half22float2(ba0);
        float2 f2 = __half22float2(ca0), f3 = __half22float2(da0);
        float2 g0 = __half22float2(aa1), g1 = __half22float2(ba1);
        float2 g2 = __half22float2(ca1), g3 = __half22float2(da1);
        float p0 = fminf(fmaxf(bf.x + (f0.x + f1.x) + (f2.x + f3.x), 0.f), 1.f);
        float p1 = fminf(fmaxf(bf.y + (f0.y + f1.y) + (f2.y + f3.y), 0.f), 1.f);
        float p2 = fminf(fmaxf(bf.z + (g0.x + g1.x) + (g2.x + g3.x), 0.f), 1.f);
        float p3 = fminf(fmaxf(bf.w + (g0.y + g1.y) + (g2.y + g3.y), 0.f), 1.f);
        const int pr = (R >= BATCH);
        const float4 wo = *(const float4*)(wcl + pr * 128);
        float contrib = p0*p0*wo.x + p1*p1*wo.y + p2*p2*wo.z + p3*p3*wo.w;

        #pragma unroll
        for (int off = 16; off; off >>= 1)
            contrib += __shfl_xor_sync(0xffffffffu, contrib, off);

        if (lane == 0)
            g_acc[(size_t)(R & (BATCH - 1)) * NSLOT + (s * 2 + pr)] = contrib;
    }
}

// ============================================================================
// Kernel 3: sum 16 contiguous partials (4x float4), add b_out, sigmoid.
// ============================================================================
__global__ __launch_bounds__(256) void finalize_kernel(const float* __restrict__ b_out,
                                                       float* __restrict__ out) {
    int b = blockIdx.x * 256 + threadIdx.x;
    if (b >= BATCH) return;
    const float4* a = (const float4*)(g_acc + (size_t)b * NSLOT);
    float4 v0 = a[0], v1 = a[1], v2 = a[2], v3 = a[3];
    float x = b_out[0]
            + ((v0.x + v0.y) + (v0.z + v0.w))
            + ((v1.x + v1.y) + (v1.z + v1.w))
            + ((v2.x + v2.y) + (v2.z + v2.w))
            + ((v3.x + v3.y) + (v3.z + v3.w));
    out[b] = 1.0f / (1.0f + __expf(-x));
}

extern "C" void kernel_launch(void* const* d_in, const int* in_sizes, int n_in,
                              void* d_out, int out_size) {
    const float* stm   = (const float*)d_in[0];
    const float* nstm  = (const float*)d_in[1];
    const float* W_ft  = (const float*)d_in[2];
    const float* b_ft  = (const float*)d_in[3];
    const float* W_out = (const float*)d_in[4];
    const float* b_out = (const float*)d_in[5];
    float* out = (float*)d_out;

    cudaFuncSetAttribute(accum_kernel,
                         cudaFuncAttributeMaxDynamicSharedMemorySize, SMEM_BYTES);

    scan_kernel<<<NROWS / 8, 256>>>(stm, nstm);                            // 4096 blocks
    accum_kernel<<<NSL * RB, THREADS, SMEM_BYTES>>>(W_ft, b_ft, W_out);    // 144 blocks
    finalize_kernel<<<(BATCH + 255) / 256, 256>>>(b_out, out);
}